// round 4
// baseline (speedup 1.0000x reference)
#include <cuda_runtime.h>
#include <cstdint>

#define NSEG 100000
#define CAP  128            // max rows per segment; Poisson(42) => P(>=128) ~ 1e-26

// static scratch (no cudaMalloc allowed)
__device__ int g_cnt[NSEG];
__device__ int g_rowid[NSEG * CAP];   // 51.2 MB bucket array

__global__ void zero_cnt_kernel() {
    int i = blockIdx.x * blockDim.x + threadIdx.x;
    if (i < NSEG) g_cnt[i] = 0;
}

// one thread per 4 rows: read int4 of index, bump cursor, drop row-id in bucket
__global__ void build_buckets_kernel(const int4* __restrict__ idx4, int n4) {
    int t = blockIdx.x * blockDim.x + threadIdx.x;
    if (t >= n4) return;
    int4 v = idx4[t];
    int base = t * 4;
    int p0 = atomicAdd(&g_cnt[v.x], 1);
    int p1 = atomicAdd(&g_cnt[v.y], 1);
    int p2 = atomicAdd(&g_cnt[v.z], 1);
    int p3 = atomicAdd(&g_cnt[v.w], 1);
    g_rowid[v.x * CAP + p0] = base + 0;
    g_rowid[v.y * CAP + p1] = base + 1;
    g_rowid[v.z * CAP + p2] = base + 2;
    g_rowid[v.w * CAP + p3] = base + 3;
}

// one warp per segment; half-warp (16 lanes) per row, 2 rows per load step.
// Software-pipelined: 4 independent 512B x-loads in flight per iteration.
__global__ void gather_kernel(const float4* __restrict__ x,
                              float* __restrict__ out) {
    int warp = (blockIdx.x * blockDim.x + threadIdx.x) >> 5;
    int lane = threadIdx.x & 31;
    if (warp >= NSEG) return;

    int s    = warp;
    int cnt  = g_cnt[s];
    int m    = min(cnt, CAP);
    int half = lane >> 4;      // 0 or 1: which row of the pair
    int q    = lane & 15;      // which float4 of the row

    const int* __restrict__ bucket = &g_rowid[s * CAP];

    float4 acc0 = make_float4(0.f, 0.f, 0.f, 0.f);
    float4 acc1 = make_float4(0.f, 0.f, 0.f, 0.f);

    int j = half;
    // main loop: 4 rows per half-warp per iteration (8 rows per warp)
    for (; j + 6 < m; j += 8) {
        // batch the row-id loads (L1 hits after first touch)
        int r0 = __ldg(&bucket[j]);
        int r1 = __ldg(&bucket[j + 2]);
        int r2 = __ldg(&bucket[j + 4]);
        int r3 = __ldg(&bucket[j + 6]);
        // 4 independent 512B warp-loads in flight
        float4 v0 = __ldg(&x[(long long)r0 * 16 + q]);
        float4 v1 = __ldg(&x[(long long)r1 * 16 + q]);
        float4 v2 = __ldg(&x[(long long)r2 * 16 + q]);
        float4 v3 = __ldg(&x[(long long)r3 * 16 + q]);
        acc0.x += v0.x; acc0.y += v0.y; acc0.z += v0.z; acc0.w += v0.w;
        acc1.x += v1.x; acc1.y += v1.y; acc1.z += v1.z; acc1.w += v1.w;
        acc0.x += v2.x; acc0.y += v2.y; acc0.z += v2.z; acc0.w += v2.w;
        acc1.x += v3.x; acc1.y += v3.y; acc1.z += v3.z; acc1.w += v3.w;
    }
    // tail
    for (; j < m; j += 2) {
        int r = __ldg(&bucket[j]);
        float4 v = __ldg(&x[(long long)r * 16 + q]);
        acc0.x += v.x; acc0.y += v.y; acc0.z += v.z; acc0.w += v.w;
    }

    acc0.x += acc1.x; acc0.y += acc1.y; acc0.z += acc1.z; acc0.w += acc1.w;

    // combine the two half-warp partial sums
    acc0.x += __shfl_down_sync(0xffffffffu, acc0.x, 16);
    acc0.y += __shfl_down_sync(0xffffffffu, acc0.y, 16);
    acc0.z += __shfl_down_sync(0xffffffffu, acc0.z, 16);
    acc0.w += __shfl_down_sync(0xffffffffu, acc0.w, 16);

    if (lane < 16) {
        float inv = 1.0f / fmaxf((float)cnt, 1.0f);
        float4 r = make_float4(acc0.x * inv, acc0.y * inv, acc0.z * inv, acc0.w * inv);
        ((float4*)out)[(long long)s * 16 + q] = r;   // writes every segment (0 if empty)
    }
}

extern "C" void kernel_launch(void* const* d_in, const int* in_sizes, int n_in,
                              void* d_out, int out_size) {
    const float4* x    = (const float4*)d_in[0];
    const int4*   idx4 = (const int4*)d_in[1];
    float* out = (float*)d_out;

    int n_rows = in_sizes[1];          // 4194304
    int n4 = n_rows / 4;

    // 1) zero cursors
    zero_cnt_kernel<<<(NSEG + 255) / 256, 256>>>();

    // 2) bucket row ids by segment
    build_buckets_kernel<<<(n4 + 255) / 256, 256>>>(idx4, n4);

    // 3) gather-reduce: one warp per segment, writes means directly
    {
        long long total_threads = (long long)NSEG * 32;
        int threads = 256;
        int blocks = (int)((total_threads + threads - 1) / threads);
        gather_kernel<<<blocks, threads>>>(x, out);
    }
}

// round 5
// speedup vs baseline: 1.0902x; 1.0902x over previous
#include <cuda_runtime.h>
#include <cstdint>

#define NSEG 100000
#define CAP  128            // max rows per segment; Poisson(42) => P(>=128) ~ 1e-26

// static scratch (no cudaMalloc allowed). Zero-initialized at module load;
// gather_kernel resets g_cnt after use so every graph replay starts clean.
__device__ int g_cnt[NSEG];
__device__ int g_rowid[NSEG * CAP];   // 51.2 MB bucket array

// one thread per 4 rows: read int4 of index, bump cursor, drop row-id in bucket
__global__ void build_buckets_kernel(const int4* __restrict__ idx4, int n4) {
    int t = blockIdx.x * blockDim.x + threadIdx.x;
    if (t >= n4) return;
    int4 v = __ldcs(&idx4[t]);          // touch-once: evict-first
    int base = t * 4;
    int p0 = atomicAdd(&g_cnt[v.x], 1);
    int p1 = atomicAdd(&g_cnt[v.y], 1);
    int p2 = atomicAdd(&g_cnt[v.z], 1);
    int p3 = atomicAdd(&g_cnt[v.w], 1);
    g_rowid[v.x * CAP + p0] = base + 0;
    g_rowid[v.y * CAP + p1] = base + 1;
    g_rowid[v.z * CAP + p2] = base + 2;
    g_rowid[v.w * CAP + p3] = base + 3;
}

// one warp per segment; lanes 0-15 handle row j, lanes 16-31 handle row j+1.
// Each lane accumulates one float4 (16B) of the 256B row. Final shfl combine,
// lanes 0-15 write the 64-float mean. No atomics. Resets g_cnt for next replay.
__global__ void gather_kernel(const float4* __restrict__ x,
                              float* __restrict__ out) {
    int warp = (blockIdx.x * blockDim.x + threadIdx.x) >> 5;
    int lane = threadIdx.x & 31;
    if (warp >= NSEG) return;

    int s    = warp;
    int cnt  = g_cnt[s];
    int m    = min(cnt, CAP);
    int half = lane >> 4;      // 0 or 1: which row of the pair
    int q    = lane & 15;      // which float4 of the row

    const int* __restrict__ bucket = &g_rowid[s * CAP];

    float4 acc = make_float4(0.f, 0.f, 0.f, 0.f);

    #pragma unroll 4
    for (int j = half; j < m; j += 2) {
        int row = __ldg(&bucket[j]);                        // broadcast per 16 lanes
        float4 v = __ldcs(&x[(long long)row * 16 + q]);     // touch-once: evict-first
        acc.x += v.x; acc.y += v.y; acc.z += v.z; acc.w += v.w;
    }

    // combine the two half-warp partial sums
    acc.x += __shfl_down_sync(0xffffffffu, acc.x, 16);
    acc.y += __shfl_down_sync(0xffffffffu, acc.y, 16);
    acc.z += __shfl_down_sync(0xffffffffu, acc.z, 16);
    acc.w += __shfl_down_sync(0xffffffffu, acc.w, 16);

    if (lane < 16) {
        float inv = 1.0f / fmaxf((float)cnt, 1.0f);
        float4 r = make_float4(acc.x * inv, acc.y * inv, acc.z * inv, acc.w * inv);
        ((float4*)out)[(long long)s * 16 + q] = r;          // writes every segment (0 if empty)
    }

    if (lane == 0) g_cnt[s] = 0;   // reset cursor for the next graph replay
}

extern "C" void kernel_launch(void* const* d_in, const int* in_sizes, int n_in,
                              void* d_out, int out_size) {
    const float4* x    = (const float4*)d_in[0];
    const int4*   idx4 = (const int4*)d_in[1];
    float* out = (float*)d_out;

    int n_rows = in_sizes[1];          // 4194304
    int n4 = n_rows / 4;

    // 1) bucket row ids by segment (g_cnt starts zeroed; gather re-zeroes it)
    build_buckets_kernel<<<(n4 + 255) / 256, 256>>>(idx4, n4);

    // 2) gather-reduce: one warp per segment, writes means directly
    {
        long long total_threads = (long long)NSEG * 32;
        int threads = 256;
        int blocks = (int)((total_threads + threads - 1) / threads);
        gather_kernel<<<blocks, threads>>>(x, out);
    }
}